// round 13
// baseline (speedup 1.0000x reference)
#include <cuda_runtime.h>
#include <cuda_bf16.h>
#include <math_constants.h>
#include <cstdint>

// CrossMHA: B=2, S=2048, DIM=1024, H=16, DK=64, heads-last layout [b,s,dk,h]
namespace {
constexpr int B_ = 2, S_ = 2048, DIM_ = 1024, H_ = 16, DK_ = 64;
}

// Scratch (static device globals; no allocation in kernel_launch)
__device__ float g_Q[B_ * S_ * DIM_];        // dec @ Wq^T, [b,s,dim]
__device__ float g_KV[B_ * S_ * 2 * DIM_];   // enc @ Wkv^T, [b,s,2*dim]
__device__ float g_Oh[B_ * S_ * DIM_];       // attention out, [b,h,s,dk]
__device__ float g_attn[B_ * S_ * DIM_];     // repacked to [b,s,dim] heads-last
// Pre-split bf16 packed-pair operands for attention (u32 = 2 bf16)
__device__ uint32_t g_Qph[B_ * H_ * S_ * 32];       // pairs along dk, hi
__device__ uint32_t g_Qpl[B_ * H_ * S_ * 32];       // lo (residual)
__device__ uint32_t g_Kph[B_ * H_ * S_ * 32];
__device__ uint32_t g_Kpl[B_ * H_ * S_ * 32];
__device__ uint32_t g_Vph[B_ * H_ * (S_ / 2) * 64]; // pairs along key
__device__ uint32_t g_Vpl[B_ * H_ * (S_ / 2) * 64];
// Bit-packed mask: word w of row (b,q) holds keys [32w,32w+32), bit l = key 32w+l
__device__ uint32_t g_mbits[B_ * S_ * (S_ / 32)];

// ===========================================================================
// Warp-level bf16 MMA helpers (base sm_80+ instructions; assemble on sm_103)
// ===========================================================================
__device__ __forceinline__ uint32_t packbf(__nv_bfloat16 lo, __nv_bfloat16 hi) {
  __nv_bfloat162 t(lo, hi);
  return *reinterpret_cast<uint32_t*>(&t);
}
__device__ __forceinline__ void split2(float x, float y, uint32_t& hi, uint32_t& lo) {
  __nv_bfloat16 bx = __float2bfloat16_rn(x);
  __nv_bfloat16 by = __float2bfloat16_rn(y);
  float rx = x - __bfloat162float(bx);
  float ry = y - __bfloat162float(by);
  hi = packbf(bx, by);
  lo = packbf(__float2bfloat16_rn(rx), __float2bfloat16_rn(ry));
}
__device__ __forceinline__ void mma16816(float* d, const uint32_t* a, const uint32_t* b) {
  asm volatile(
      "mma.sync.aligned.m16n8k16.row.col.f32.bf16.bf16.f32 "
      "{%0,%1,%2,%3}, {%4,%5,%6,%7}, {%8,%9}, {%0,%1,%2,%3};"
      : "+f"(d[0]), "+f"(d[1]), "+f"(d[2]), "+f"(d[3])
      : "r"(a[0]), "r"(a[1]), "r"(a[2]), "r"(a[3]), "r"(b[0]), "r"(b[1]));
}
__device__ __forceinline__ uint32_t smem_u32(const void* p) {
  uint32_t a;
  asm("{ .reg .u64 t; cvta.to.shared.u64 t, %1; cvt.u32.u64 %0, t; }"
      : "=r"(a) : "l"(p));
  return a;
}
__device__ __forceinline__ void cpasync16(uint32_t dst, const void* src) {
  asm volatile("cp.async.ca.shared.global [%0], [%1], 16;" :: "r"(dst), "l"(src));
}
__device__ __forceinline__ void cpasync8(uint32_t dst, const void* src) {
  asm volatile("cp.async.ca.shared.global [%0], [%1], 8;" :: "r"(dst), "l"(src));
}
#define CPA_COMMIT() asm volatile("cp.async.commit_group;" ::: "memory")
#define CPA_WAIT(n) asm volatile("cp.async.wait_group %0;" :: "n"(n) : "memory")
// Forced-early global load (pins issue position vs the asm-volatile MMAs)
__device__ __forceinline__ void ldg128(float4& v, const float* p) {
  asm volatile("ld.global.nc.v4.f32 {%0,%1,%2,%3}, [%4];"
               : "=f"(v.x), "=f"(v.y), "=f"(v.z), "=f"(v.w) : "l"(p));
}

// ---------------------------------------------------------------------------
// Profiler-aiming dummy (ncu captures the 4th launch)
// ---------------------------------------------------------------------------
__global__ void dummy_k() {}

// ---------------------------------------------------------------------------
// Mask bit-pack: int32 [B,S,S] -> u32 bitmask [B*S][S/32] via warp ballot.
// ---------------------------------------------------------------------------
__global__ __launch_bounds__(256)
void mask_pack(const int* __restrict__ mask) {
  const int lane = threadIdx.x & 31;
  const int W = blockIdx.x * 8 + (threadIdx.x >> 5);   // global warp id
#pragma unroll 4
  for (int i = 0; i < 32; ++i) {
    int widx = W * 32 + i;
    int v = mask[(size_t)widx * 32 + lane];
    uint32_t bits = __ballot_sync(0xffffffffu, v != 0);
    if (lane == 0) g_mbits[widx] = bits;
  }
}

// ===========================================================================
// bf16-split GEMM on mma.sync: C[M,N] = A[M,K] * W[N,K]^T  (fp32 in/out)
// Block tile 128x128, 8 warps (2 M x 4 N), warp tile 64x32.
// CHANGE vs R12: load/compute rotation — STS consumes regs loaded last iter;
// next chunk's A loads forced-early (before MMA phase) via asm; W loads at
// loop bottom so their latency overlaps only the loop-top barrier.
// ===========================================================================
namespace {
constexpr int GK = 1024;
constexpr int NCHUNK = GK / 64;
constexpr int R4 = 36;                 // smem row stride in b32 (144 bytes)
constexpr int TILE32 = 128 * R4;
constexpr int GEMM_SMEM = 4 * TILE32 * 4;  // 73728 B
}

__global__ __launch_bounds__(256, 2)
void gemm_tc(const float* __restrict__ A, const float* __restrict__ W,
             float* __restrict__ C, int N) {
  extern __shared__ uint32_t sm[];
  uint32_t* const sAhi = sm;
  uint32_t* const sAlo = sm + TILE32;
  uint32_t* const sWhi = sm + 2 * TILE32;
  uint32_t* const sWlo = sm + 3 * TILE32;

  const int tid = threadIdx.x;
  const int lane = tid & 31;
  const int wid = tid >> 5;
  const int g = lane >> 2;
  const int t = lane & 3;
  const int warp_m = wid & 1;
  const int warp_n = wid >> 1;
  const int bm = blockIdx.y * 128;
  const int bn = blockIdx.x * 128;

  float acc[4][4][4];
#pragma unroll
  for (int mt = 0; mt < 4; mt++)
#pragma unroll
    for (int nt = 0; nt < 4; nt++)
#pragma unroll
      for (int c = 0; c < 4; c++) acc[mt][nt][c] = 0.f;

  const uint32_t* const Awhi = sAhi + (warp_m * 64) * R4;
  const uint32_t* const Awlo = sAlo + (warp_m * 64) * R4;
  const uint32_t* const Bwhi = sWhi + (warp_n * 32) * R4;
  const uint32_t* const Bwlo = sWlo + (warp_n * 32) * R4;

  float4 av[8], wv[8];
  // prologue: chunk 0 into registers
#pragma unroll
  for (int l = 0; l < 8; ++l) {
    int idx = tid + l * 256;
    int r = idx >> 4;
    int c4 = idx & 15;
    av[l] = *(const float4*)(A + (size_t)(bm + r) * GK + c4 * 4);
    wv[l] = *(const float4*)(W + (size_t)(bn + r) * GK + c4 * 4);
  }

  for (int ch = 0; ch < NCHUNK; ++ch) {
    __syncthreads();   // previous chunk's MMAs done reading smem
#pragma unroll
    for (int l = 0; l < 8; ++l) {
      int idx = tid + l * 256;
      int r = idx >> 4;
      int c4 = idx & 15;
      int base = r * R4 + c4 * 2;
      uint32_t h0, l0, h1, l1;
      split2(av[l].x, av[l].y, h0, l0);
      split2(av[l].z, av[l].w, h1, l1);
      sAhi[base] = h0; sAhi[base + 1] = h1;
      sAlo[base] = l0; sAlo[base + 1] = l1;
      split2(wv[l].x, wv[l].y, h0, l0);
      split2(wv[l].z, wv[l].w, h1, l1);
      sWhi[base] = h0; sWhi[base + 1] = h1;
      sWlo[base] = l0; sWlo[base + 1] = l1;
    }
    __syncthreads();

    const int kn = (ch + 1) * 64;
    if (ch + 1 < NCHUNK) {
      // forced-early A prefetch: issues before the MMA phase, consumed at
      // next iteration's STS -> latency hidden under ~1500 cyc of MMAs
#pragma unroll
      for (int l = 0; l < 8; ++l) {
        int idx = tid + l * 256;
        int r = idx >> 4;
        int c4 = idx & 15;
        ldg128(av[l], A + (size_t)(bm + r) * GK + kn + c4 * 4);
      }
    }

#pragma unroll
    for (int ks = 0; ks < 4; ++ks) {
      const int kb = ks * 8;
      uint32_t bh[4][2], bl[4][2];
#pragma unroll
      for (int nt = 0; nt < 4; ++nt) {
        int o = (nt * 8 + g) * R4 + kb + t;
        bh[nt][0] = Bwhi[o]; bh[nt][1] = Bwhi[o + 4];
        bl[nt][0] = Bwlo[o]; bl[nt][1] = Bwlo[o + 4];
      }
#pragma unroll
      for (int mt = 0; mt < 4; ++mt) {
        int o0 = (mt * 16 + g) * R4 + kb + t;
        int o1 = o0 + 8 * R4;
        uint32_t ah[4], al[4];
        ah[0] = Awhi[o0]; ah[1] = Awhi[o1]; ah[2] = Awhi[o0 + 4]; ah[3] = Awhi[o1 + 4];
        al[0] = Awlo[o0]; al[1] = Awlo[o1]; al[2] = Awlo[o0 + 4]; al[3] = Awlo[o1 + 4];
#pragma unroll
        for (int nt = 0; nt < 4; ++nt) {
          mma16816(acc[mt][nt], ah, bh[nt]);
          mma16816(acc[mt][nt], ah, bl[nt]);
          mma16816(acc[mt][nt], al, bh[nt]);
        }
      }
    }

    if (ch + 1 < NCHUNK) {
      // W loads at loop bottom: exposure = one barrier, not full latency
#pragma unroll
      for (int l = 0; l < 8; ++l) {
        int idx = tid + l * 256;
        int r = idx >> 4;
        int c4 = idx & 15;
        wv[l] = *(const float4*)(W + (size_t)(bn + r) * GK + kn + c4 * 4);
      }
    }
  }

#pragma unroll
  for (int mt = 0; mt < 4; ++mt) {
    int row0 = bm + warp_m * 64 + mt * 16 + g;
#pragma unroll
    for (int nt = 0; nt < 4; ++nt) {
      int col = bn + warp_n * 32 + nt * 8 + 2 * t;
      *(float2*)(C + (size_t)row0 * N + col) = make_float2(acc[mt][nt][0], acc[mt][nt][1]);
      *(float2*)(C + (size_t)(row0 + 8) * N + col) = make_float2(acc[mt][nt][2], acc[mt][nt][3]);
    }
  }
}

// ---------------------------------------------------------------------------
// Repack + pre-split: [b,s, d*16+h] fp32 -> packed bf16-pair hi/lo arrays.
// One block per (b, s-pair). Q/K: pairs along dk. V: pairs along key.
// ---------------------------------------------------------------------------
__global__ __launch_bounds__(256)
void repack_qkv() {
  __shared__ float sq[2][1056], sk[2][1056], sv[2][1056];
  const int u = blockIdx.x;            // 0 .. B*S/2-1
  const int b = u >> 10;
  const int sp = u & 1023;
  const int s0 = sp * 2;
  const int tid = threadIdx.x;
  const float* q0  = g_Q  + ((size_t)b * S_ + s0) * DIM_;
  const float* kv0 = g_KV + ((size_t)b * S_ + s0) * 2 * DIM_;
#pragma unroll
  for (int l = 0; l < 8; l++) {
    int i = tid + l * 256;
    int r = i >> 10, c = i & 1023;
    int a = c + (c >> 5);
    sq[r][a] = q0[(size_t)r * DIM_ + c];
    sk[r][a] = kv0[(size_t)r * 2 * DIM_ + c];
    sv[r][a] = kv0[(size_t)r * 2 * DIM_ + DIM_ + c];
  }
  __syncthreads();
  // Q/K: out[(b,h, s0+r)][dd] = pack(x[32dd+h], x[32dd+16+h])
#pragma unroll
  for (int l = 0; l < 4; l++) {
    int idx = tid + l * 256;
    int r = idx >> 9, rem = idx & 511;
    int h = rem >> 5, dd = rem & 31;
    int a0 = 32 * dd + h;       a0 += a0 >> 5;
    int a1 = 32 * dd + 16 + h;  a1 += a1 >> 5;
    size_t o = ((size_t)(b * H_ + h) * S_ + s0 + r) * 32 + dd;
    uint32_t hi, lo;
    split2(sq[r][a0], sq[r][a1], hi, lo);
    g_Qph[o] = hi; g_Qpl[o] = lo;
    split2(sk[r][a0], sk[r][a1], hi, lo);
    g_Kph[o] = hi; g_Kpl[o] = lo;
  }
  // V: out[(b,h, sp)][d] = pack(V[s0][d], V[s0+1][d])
#pragma unroll
  for (int l = 0; l < 4; l++) {
    int idx = tid + l * 256;
    int h = idx >> 6, d = idx & 63;
    int a = d * 16 + h; a += a >> 5;
    uint32_t hi, lo;
    split2(sv[0][a], sv[1][a], hi, lo);
    size_t o = ((size_t)(b * H_ + h) * (S_ / 2) + sp) * 64 + d;
    g_Vph[o] = hi; g_Vpl[o] = lo;
  }
}

// ---------------------------------------------------------------------------
// Unpack: [b,h,s,d] -> [b,s, d*16+h]
// ---------------------------------------------------------------------------
__global__ void unpack_o() {
  __shared__ float buf[1056];
  const int bs = blockIdx.x;
  const int b = bs >> 11;
  const int s = bs & (S_ - 1);
  const int tid = threadIdx.x;
#pragma unroll
  for (int l = 0; l < 4; l++) {
    int idx = tid + l * 256;
    int h = idx >> 6, d = idx & 63;
    int a = d * H_ + h;
    buf[a + (a >> 5)] = g_Oh[((size_t)(b * H_ + h) * S_ + s) * DK_ + d];
  }
  __syncthreads();
#pragma unroll
  for (int l = 0; l < 4; l++) {
    int i = tid + l * 256;
    g_attn[(size_t)bs * DIM_ + i] = buf[i + (i >> 5)];
  }
}

// ===========================================================================
// Tensor-core flash attention, cp.async double-buffered, flat softmax,
// bitmask streamed through the pipeline. (unchanged from R12)
// ===========================================================================
namespace {
constexpr int AQ = 0;
constexpr int AK = 9216;
constexpr int AV = 18432;
constexpr int AM = 27648;
constexpr int ATTN_SMEM = 28160 * 4;   // 112640 B
constexpr float EXC = 0.125f * 1.4426950408889634f;  // (1/8)*log2(e)
}

__global__ __launch_bounds__(256, 2)
void attn_mma() {
  extern __shared__ uint32_t smem[];
  const uint32_t sb = smem_u32(smem);
  const int qt = blockIdx.x, h = blockIdx.y, b = blockIdx.z;
  const int tid = threadIdx.x;
  const int lane = tid & 31, w = tid >> 5;
  const int g = lane >> 2, t = lane & 3;
  const int bh = b * H_ + h;
  const uint32_t* const Qsh = g_Qph + ((size_t)bh * S_ + qt * 128) * 32;
  const uint32_t* const Qsl = g_Qpl + ((size_t)bh * S_ + qt * 128) * 32;
  const uint32_t* const Ksh = g_Kph + (size_t)bh * S_ * 32;
  const uint32_t* const Ksl = g_Kpl + (size_t)bh * S_ * 32;
  const uint32_t* const Vsh = g_Vph + (size_t)bh * (S_ / 2) * 64;
  const uint32_t* const Vsl = g_Vpl + (size_t)bh * (S_ / 2) * 64;
  const uint32_t* const Mb = g_mbits + (size_t)(b * S_ + qt * 128) * (S_ / 32);

  // ---- prologue: Q tile + key-tile 0 (K, V, mask) into stage 0 ----
#pragma unroll
  for (int l = 0; l < 4; l++) {
    int idx = tid + l * 256;        // 0..1023
    int r = idx >> 3, c = (idx & 7) * 4;
    cpasync16(sb + (AQ + r * R4 + c) * 4, Qsh + r * 32 + c);
    cpasync16(sb + (AQ + 4608 + r * R4 + c) * 4, Qsl + r * 32 + c);
  }
#pragma unroll
  for (int l = 0; l < 2; l++) {
    int idx = tid + l * 256;      // 0..511
    int r = idx >> 3, c = (idx & 7) * 4;
    uint32_t d = sb + (AK + r * R4 + c) * 4;
    cpasync16(d, Ksh + r * 32 + c);
    cpasync16(d + 2304 * 4, Ksl + r * 32 + c);
    int rv = idx >> 4, cv = (idx & 15) * 4;
    uint32_t dv = sb + (AV + rv * 72 + cv) * 4;
    cpasync16(dv, Vsh + rv * 64 + cv);
    cpasync16(dv + 2304 * 4, Vsl + rv * 64 + cv);
  }
  if (tid < 128)
    cpasync8(sb + (AM + tid * 2) * 4, Mb + (size_t)tid * (S_ / 32));
  CPA_COMMIT();

  float ls0 = 0.f, ls1 = 0.f;
  float oacc[8][4];
#pragma unroll
  for (int jd = 0; jd < 8; jd++)
#pragma unroll
    for (int c = 0; c < 4; c++) oacc[jd][c] = 0.f;

  const uint32_t* const Qbh = smem + AQ + (w * 16) * R4;
  const uint32_t* const Qbl = Qbh + 4608;

  for (int it = 0; it < S_ / 64; ++it) {
    if (it + 1 < S_ / 64) {
      const int kn = (it + 1) * 64;
      const int st = (it + 1) & 1;
#pragma unroll
      for (int l = 0; l < 2; l++) {
        int idx = tid + l * 256;
        int r = idx >> 3, c = (idx & 7) * 4;
        uint32_t d = sb + (AK + st * 4608 + r * R4 + c) * 4;
        cpasync16(d, Ksh + (size_t)(kn + r) * 32 + c);
        cpasync16(d + 2304 * 4, Ksl + (size_t)(kn + r) * 32 + c);
        int rv = idx >> 4, cv = (idx & 15) * 4;
        uint32_t dv = sb + (AV + st * 4608 + rv * 72 + cv) * 4;
        cpasync16(dv, Vsh + (size_t)(kn / 2 + rv) * 64 + cv);
        cpasync16(dv + 2304 * 4, Vsl + (size_t)(kn / 2 + rv) * 64 + cv);
      }
      if (tid < 128)
        cpasync8(sb + (AM + st * 256 + tid * 2) * 4,
                 Mb + (size_t)tid * (S_ / 32) + 2 * (it + 1));
      CPA_COMMIT();
      CPA_WAIT(1);
    } else {
      CPA_WAIT(0);
    }
    __syncthreads();

    const uint32_t* const Khi = smem + AK + (it & 1) * 4608;
    const uint32_t* const Klo = Khi + 2304;
    const uint32_t* const Vhp = smem + AV + (it & 1) * 4608;
    const uint32_t* const Vlp = Vhp + 2304;

    // mask bits for this tile (rows g and g+8)
    const uint32_t* const Mst = smem + AM + (it & 1) * 256;
    uint2 mg  = *(const uint2*)&Mst[(w * 16 + g) * 2];
    uint2 mg8 = *(const uint2*)&Mst[(w * 16 + g + 8) * 2];

    // ---- S = Q K^T (3-MMA split) ----
    float sf[8][4];
#pragma unroll
    for (int j = 0; j < 8; j++)
#pragma unroll
      for (int c = 0; c < 4; c++) sf[j][c] = 0.f;

#pragma unroll
    for (int ks = 0; ks < 4; ++ks) {
      const int kb = ks * 8;
      uint32_t ah[4], al[4];
      ah[0] = Qbh[g * R4 + kb + t];       ah[1] = Qbh[(g + 8) * R4 + kb + t];
      ah[2] = Qbh[g * R4 + kb + t + 4];   ah[3] = Qbh[(g + 8) * R4 + kb + t + 4];
      al[0] = Qbl[g * R4 + kb + t];       al[1] = Qbl[(g + 8) * R4 + kb + t];
      al[2] = Qbl[g * R4 + kb + t + 4];   al[3] = Qbl[(g + 8) * R4 + kb + t + 4];
#pragma unroll
      for (int j = 0; j < 8; j++) {
        int o = (j * 8 + g) * R4 + kb + t;
        uint32_t bh2[2] = {Khi[o], Khi[o + 4]};
        uint32_t bl2[2] = {Klo[o], Klo[o + 4]};
        mma16816(sf[j], ah, bh2);
        mma16816(sf[j], ah, bl2);
        mma16816(sf[j], al, bh2);
      }
    }

    // ---- mask bits -> p = exp2(score*EXC) or 0; accumulate row sums ----
#pragma unroll
    for (int j = 0; j < 8; j++) {
      const int pos = 8 * (j & 3) + 2 * t;
      const uint32_t wg  = (j < 4) ? mg.x : mg.y;
      const uint32_t wg8 = (j < 4) ? mg8.x : mg8.y;
      sf[j][0] = ((wg >> pos) & 1u)       ? exp2f(sf[j][0] * EXC) : 0.f;
      sf[j][1] = ((wg >> (pos + 1)) & 1u) ? exp2f(sf[j][1] * EXC) : 0.f;
      sf[j][2] = ((wg8 >> pos) & 1u)      ? exp2f(sf[j][2] * EXC) : 0.f;
      sf[j][3] = ((wg8 >> (pos + 1)) & 1u)? exp2f(sf[j][3] * EXC) : 0.f;
      ls0 += sf[j][0] + sf[j][1];
      ls1 += sf[j][2] + sf[j][3];
    }

    // ---- O += P V (3-MMA split; P from registers) ----
#pragma unroll
    for (int ks = 0; ks < 4; ++ks) {
      uint32_t ah[4], al[4];
      split2(sf[2 * ks][0], sf[2 * ks][1], ah[0], al[0]);
      split2(sf[2 * ks][2], sf[2 * ks][3], ah[1], al[1]);
      split2(sf[2 * ks + 1][0], sf[2 * ks + 1][1], ah[2], al[2]);
      split2(sf[2 * ks + 1][2], sf[2 * ks + 1][3], ah[3], al[3]);
#pragma unroll
      for (int jd = 0; jd < 8; jd++) {
        int o = (ks * 8 + t) * 72 + jd * 8 + g;
        uint32_t bh2[2] = {Vhp[o], Vhp[o + 4 * 72]};
        uint32_t bl2[2] = {Vlp[o], Vlp[o + 4 * 72]};
        mma16816(oacc[jd], ah, bh2);
        mma16816(oacc[jd], ah, bl2);
        mma16816(oacc[jd], al, bh2);
      }
    }
    __syncthreads();   // stage (it&1) consumed before it+2 refills it
  }

  // ---- epilogue: reduce row sums across t-lanes, normalize, store ----
  ls0 += __shfl_xor_sync(0xffffffffu, ls0, 1);
  ls0 += __shfl_xor_sync(0xffffffffu, ls0, 2);
  ls1 += __shfl_xor_sync(0xffffffffu, ls1, 1);
  ls1 += __shfl_xor_sync(0xffffffffu, ls1, 2);
  float inv0 = 1.f / ls0, inv1 = 1.f / ls1;
  float* Op = g_Oh + ((size_t)bh * S_ + qt * 128 + w * 16) * DK_;
#pragma unroll
  for (int jd = 0; jd < 8; jd++) {
    *(float2*)(Op + (size_t)g * DK_ + jd * 8 + 2 * t) =
        make_float2(oacc[jd][0] * inv0, oacc[jd][1] * inv0);
    *(float2*)(Op + (size_t)(g + 8) * DK_ + jd * 8 + 2 * t) =
        make_float2(oacc[jd][2] * inv1, oacc[jd][3] * inv1);
  }
}

// ---------------------------------------------------------------------------
extern "C" void kernel_launch(void* const* d_in, const int* in_sizes, int n_in,
                              void* d_out, int out_size) {
  (void)in_sizes; (void)n_in; (void)out_size;
  const float* dec  = (const float*)d_in[0];
  const float* enc  = (const float*)d_in[1];
  const float* Wq   = (const float*)d_in[2];
  const float* Wkv  = (const float*)d_in[3];
  const float* Wo   = (const float*)d_in[4];
  const int*   mask = (const int*)d_in[5];
  float* out = (float*)d_out;

  float *Qp = nullptr, *KVp = nullptr, *attnp = nullptr;
  cudaGetSymbolAddress((void**)&Qp, g_Q);
  cudaGetSymbolAddress((void**)&KVp, g_KV);
  cudaGetSymbolAddress((void**)&attnp, g_attn);

  cudaFuncSetAttribute(gemm_tc, cudaFuncAttributeMaxDynamicSharedMemorySize, GEMM_SMEM);
  cudaFuncSetAttribute(attn_mma, cudaFuncAttributeMaxDynamicSharedMemorySize, ATTN_SMEM);

  const int M = B_ * S_;  // 4096
  // Launch order places the KV GEMM 4th: ncu captures the 4th launch.
  gemm_tc<<<dim3(DIM_ / 128, M / 128), 256, GEMM_SMEM>>>(dec, Wq, Qp, DIM_);
  mask_pack<<<B_ * S_ * (S_ / 32) / (32 * 8), 256>>>(mask);
  dummy_k<<<1, 32>>>();
  gemm_tc<<<dim3(2 * DIM_ / 128, M / 128), 256, GEMM_SMEM>>>(enc, Wkv, KVp, 2 * DIM_);
  repack_qkv<<<M / 2, 256>>>();
  attn_mma<<<dim3(S_ / 128, H_, B_), 256, ATTN_SMEM>>>();
  unpack_o<<<M, 256>>>();
  gemm_tc<<<dim3(DIM_ / 128, M / 128), 256, GEMM_SMEM>>>(attnp, Wo, out, DIM_);
}

// round 14
// speedup vs baseline: 1.1105x; 1.1105x over previous
#include <cuda_runtime.h>
#include <cuda_bf16.h>
#include <math_constants.h>
#include <cstdint>

// CrossMHA: B=2, S=2048, DIM=1024, H=16, DK=64, heads-last layout [b,s,dk,h]
namespace {
constexpr int B_ = 2, S_ = 2048, DIM_ = 1024, H_ = 16, DK_ = 64;
}

// Scratch (static device globals; no allocation in kernel_launch)
__device__ float g_Q[B_ * S_ * DIM_];        // dec @ Wq^T, [b,s,dim]
__device__ float g_KV[B_ * S_ * 2 * DIM_];   // enc @ Wkv^T, [b,s,2*dim]
__device__ float g_Oh[B_ * S_ * DIM_];       // attention out, [b,h,s,dk]
__device__ float g_attn[B_ * S_ * DIM_];     // repacked to [b,s,dim] heads-last
// Pre-split bf16 packed-pair operands for attention (u32 = 2 bf16)
__device__ uint32_t g_Qph[B_ * H_ * S_ * 32];       // pairs along dk, hi
__device__ uint32_t g_Qpl[B_ * H_ * S_ * 32];       // lo (residual)
__device__ uint32_t g_Kph[B_ * H_ * S_ * 32];
__device__ uint32_t g_Kpl[B_ * H_ * S_ * 32];
__device__ uint32_t g_Vph[B_ * H_ * (S_ / 2) * 64]; // pairs along key
__device__ uint32_t g_Vpl[B_ * H_ * (S_ / 2) * 64];
// Bit-packed mask: word w of row (b,q) holds keys [32w,32w+32), bit l = key 32w+l
__device__ uint32_t g_mbits[B_ * S_ * (S_ / 32)];

// ===========================================================================
// Warp-level bf16 MMA helpers (base sm_80+ instructions; assemble on sm_103)
// ===========================================================================
__device__ __forceinline__ uint32_t packbf(__nv_bfloat16 lo, __nv_bfloat16 hi) {
  __nv_bfloat162 t(lo, hi);
  return *reinterpret_cast<uint32_t*>(&t);
}
__device__ __forceinline__ void split2(float x, float y, uint32_t& hi, uint32_t& lo) {
  __nv_bfloat16 bx = __float2bfloat16_rn(x);
  __nv_bfloat16 by = __float2bfloat16_rn(y);
  float rx = x - __bfloat162float(bx);
  float ry = y - __bfloat162float(by);
  hi = packbf(bx, by);
  lo = packbf(__float2bfloat16_rn(rx), __float2bfloat16_rn(ry));
}
__device__ __forceinline__ void mma16816(float* d, const uint32_t* a, const uint32_t* b) {
  asm volatile(
      "mma.sync.aligned.m16n8k16.row.col.f32.bf16.bf16.f32 "
      "{%0,%1,%2,%3}, {%4,%5,%6,%7}, {%8,%9}, {%0,%1,%2,%3};"
      : "+f"(d[0]), "+f"(d[1]), "+f"(d[2]), "+f"(d[3])
      : "r"(a[0]), "r"(a[1]), "r"(a[2]), "r"(a[3]), "r"(b[0]), "r"(b[1]));
}
__device__ __forceinline__ uint32_t smem_u32(const void* p) {
  uint32_t a;
  asm("{ .reg .u64 t; cvta.to.shared.u64 t, %1; cvt.u32.u64 %0, t; }"
      : "=r"(a) : "l"(p));
  return a;
}
__device__ __forceinline__ void cpasync16(uint32_t dst, const void* src) {
  asm volatile("cp.async.ca.shared.global [%0], [%1], 16;" :: "r"(dst), "l"(src));
}
__device__ __forceinline__ void cpasync8(uint32_t dst, const void* src) {
  asm volatile("cp.async.ca.shared.global [%0], [%1], 8;" :: "r"(dst), "l"(src));
}
#define CPA_COMMIT() asm volatile("cp.async.commit_group;" ::: "memory")
#define CPA_WAIT(n) asm volatile("cp.async.wait_group %0;" :: "n"(n) : "memory")

// ---------------------------------------------------------------------------
// Profiler-aiming dummy (ncu captures the 4th launch)
// ---------------------------------------------------------------------------
__global__ void dummy_k() {}

// ---------------------------------------------------------------------------
// Mask bit-pack: int32 [B,S,S] -> u32 bitmask [B*S][S/32] via warp ballot.
// ---------------------------------------------------------------------------
__global__ __launch_bounds__(256)
void mask_pack(const int* __restrict__ mask) {
  const int lane = threadIdx.x & 31;
  const int W = blockIdx.x * 8 + (threadIdx.x >> 5);   // global warp id
#pragma unroll 4
  for (int i = 0; i < 32; ++i) {
    int widx = W * 32 + i;
    int v = mask[(size_t)widx * 32 + lane];
    uint32_t bits = __ballot_sync(0xffffffffu, v != 0);
    if (lane == 0) g_mbits[widx] = bits;
  }
}

// ===========================================================================
// bf16-split GEMM on mma.sync: C[M,N] = A[M,K] * W[N,K]^T  (fp32 in/out)
// Block tile 128x128, 8 warps (2 M x 4 N), warp tile 64x32.  (R12 version —
// R13's register-prefetch rotation spilled and regressed; reverted.)
// ===========================================================================
namespace {
constexpr int GK = 1024;
constexpr int NCHUNK = GK / 64;
constexpr int R4 = 36;                 // smem row stride in b32 (144 bytes)
constexpr int TILE32 = 128 * R4;
constexpr int GEMM_SMEM = 4 * TILE32 * 4;  // 73728 B
}

__global__ __launch_bounds__(256, 2)
void gemm_tc(const float* __restrict__ A, const float* __restrict__ W,
             float* __restrict__ C, int N) {
  extern __shared__ uint32_t sm[];
  uint32_t* const sAhi = sm;
  uint32_t* const sAlo = sm + TILE32;
  uint32_t* const sWhi = sm + 2 * TILE32;
  uint32_t* const sWlo = sm + 3 * TILE32;

  const int tid = threadIdx.x;
  const int lane = tid & 31;
  const int wid = tid >> 5;
  const int g = lane >> 2;
  const int t = lane & 3;
  const int warp_m = wid & 1;
  const int warp_n = wid >> 1;
  const int bm = blockIdx.y * 128;
  const int bn = blockIdx.x * 128;

  float acc[4][4][4];
#pragma unroll
  for (int mt = 0; mt < 4; mt++)
#pragma unroll
    for (int nt = 0; nt < 4; nt++)
#pragma unroll
      for (int c = 0; c < 4; c++) acc[mt][nt][c] = 0.f;

  const uint32_t* const Awhi = sAhi + (warp_m * 64) * R4;
  const uint32_t* const Awlo = sAlo + (warp_m * 64) * R4;
  const uint32_t* const Bwhi = sWhi + (warp_n * 32) * R4;
  const uint32_t* const Bwlo = sWlo + (warp_n * 32) * R4;

  for (int ch = 0; ch < NCHUNK; ++ch) {
    const int k0 = ch * 64;
    float4 av[8], wv[8];
#pragma unroll
    for (int l = 0; l < 8; ++l) {
      int idx = tid + l * 256;
      int r = idx >> 4;
      int c4 = idx & 15;
      av[l] = *(const float4*)(A + (size_t)(bm + r) * GK + k0 + c4 * 4);
      wv[l] = *(const float4*)(W + (size_t)(bn + r) * GK + k0 + c4 * 4);
    }
    __syncthreads();
#pragma unroll
    for (int l = 0; l < 8; ++l) {
      int idx = tid + l * 256;
      int r = idx >> 4;
      int c4 = idx & 15;
      int base = r * R4 + c4 * 2;
      uint32_t h0, l0, h1, l1;
      split2(av[l].x, av[l].y, h0, l0);
      split2(av[l].z, av[l].w, h1, l1);
      sAhi[base] = h0; sAhi[base + 1] = h1;
      sAlo[base] = l0; sAlo[base + 1] = l1;
      split2(wv[l].x, wv[l].y, h0, l0);
      split2(wv[l].z, wv[l].w, h1, l1);
      sWhi[base] = h0; sWhi[base + 1] = h1;
      sWlo[base] = l0; sWlo[base + 1] = l1;
    }
    __syncthreads();
#pragma unroll
    for (int ks = 0; ks < 4; ++ks) {
      const int kb = ks * 8;
      uint32_t bh[4][2], bl[4][2];
#pragma unroll
      for (int nt = 0; nt < 4; ++nt) {
        int o = (nt * 8 + g) * R4 + kb + t;
        bh[nt][0] = Bwhi[o]; bh[nt][1] = Bwhi[o + 4];
        bl[nt][0] = Bwlo[o]; bl[nt][1] = Bwlo[o + 4];
      }
#pragma unroll
      for (int mt = 0; mt < 4; ++mt) {
        int o0 = (mt * 16 + g) * R4 + kb + t;
        int o1 = o0 + 8 * R4;
        uint32_t ah[4], al[4];
        ah[0] = Awhi[o0]; ah[1] = Awhi[o1]; ah[2] = Awhi[o0 + 4]; ah[3] = Awhi[o1 + 4];
        al[0] = Awlo[o0]; al[1] = Awlo[o1]; al[2] = Awlo[o0 + 4]; al[3] = Awlo[o1 + 4];
#pragma unroll
        for (int nt = 0; nt < 4; ++nt) {
          mma16816(acc[mt][nt], ah, bh[nt]);
          mma16816(acc[mt][nt], ah, bl[nt]);
          mma16816(acc[mt][nt], al, bh[nt]);
        }
      }
    }
  }

#pragma unroll
  for (int mt = 0; mt < 4; ++mt) {
    int row0 = bm + warp_m * 64 + mt * 16 + g;
#pragma unroll
    for (int nt = 0; nt < 4; ++nt) {
      int col = bn + warp_n * 32 + nt * 8 + 2 * t;
      *(float2*)(C + (size_t)row0 * N + col) = make_float2(acc[mt][nt][0], acc[mt][nt][1]);
      *(float2*)(C + (size_t)(row0 + 8) * N + col) = make_float2(acc[mt][nt][2], acc[mt][nt][3]);
    }
  }
}

// ---------------------------------------------------------------------------
// Repack + pre-split: [b,s, d*16+h] fp32 -> packed bf16-pair hi/lo arrays.
// One block per (b, s-pair). Q/K: pairs along dk. V: pairs along key.
// ---------------------------------------------------------------------------
__global__ __launch_bounds__(256)
void repack_qkv() {
  __shared__ float sq[2][1056], sk[2][1056], sv[2][1056];
  const int u = blockIdx.x;            // 0 .. B*S/2-1
  const int b = u >> 10;
  const int sp = u & 1023;
  const int s0 = sp * 2;
  const int tid = threadIdx.x;
  const float* q0  = g_Q  + ((size_t)b * S_ + s0) * DIM_;
  const float* kv0 = g_KV + ((size_t)b * S_ + s0) * 2 * DIM_;
#pragma unroll
  for (int l = 0; l < 8; l++) {
    int i = tid + l * 256;
    int r = i >> 10, c = i & 1023;
    int a = c + (c >> 5);
    sq[r][a] = q0[(size_t)r * DIM_ + c];
    sk[r][a] = kv0[(size_t)r * 2 * DIM_ + c];
    sv[r][a] = kv0[(size_t)r * 2 * DIM_ + DIM_ + c];
  }
  __syncthreads();
  // Q/K: out[(b,h, s0+r)][dd] = pack(x[32dd+h], x[32dd+16+h])
#pragma unroll
  for (int l = 0; l < 4; l++) {
    int idx = tid + l * 256;
    int r = idx >> 9, rem = idx & 511;
    int h = rem >> 5, dd = rem & 31;
    int a0 = 32 * dd + h;       a0 += a0 >> 5;
    int a1 = 32 * dd + 16 + h;  a1 += a1 >> 5;
    size_t o = ((size_t)(b * H_ + h) * S_ + s0 + r) * 32 + dd;
    uint32_t hi, lo;
    split2(sq[r][a0], sq[r][a1], hi, lo);
    g_Qph[o] = hi; g_Qpl[o] = lo;
    split2(sk[r][a0], sk[r][a1], hi, lo);
    g_Kph[o] = hi; g_Kpl[o] = lo;
  }
  // V: out[(b,h, sp)][d] = pack(V[s0][d], V[s0+1][d])
#pragma unroll
  for (int l = 0; l < 4; l++) {
    int idx = tid + l * 256;
    int h = idx >> 6, d = idx & 63;
    int a = d * 16 + h; a += a >> 5;
    uint32_t hi, lo;
    split2(sv[0][a], sv[1][a], hi, lo);
    size_t o = ((size_t)(b * H_ + h) * (S_ / 2) + sp) * 64 + d;
    g_Vph[o] = hi; g_Vpl[o] = lo;
  }
}

// ---------------------------------------------------------------------------
// Unpack: [b,h,s,d] -> [b,s, d*16+h]
// ---------------------------------------------------------------------------
__global__ void unpack_o() {
  __shared__ float buf[1056];
  const int bs = blockIdx.x;
  const int b = bs >> 11;
  const int s = bs & (S_ - 1);
  const int tid = threadIdx.x;
#pragma unroll
  for (int l = 0; l < 4; l++) {
    int idx = tid + l * 256;
    int h = idx >> 6, d = idx & 63;
    int a = d * H_ + h;
    buf[a + (a >> 5)] = g_Oh[((size_t)(b * H_ + h) * S_ + s) * DK_ + d];
  }
  __syncthreads();
#pragma unroll
  for (int l = 0; l < 4; l++) {
    int i = tid + l * 256;
    g_attn[(size_t)bs * DIM_ + i] = buf[i + (i >> 5)];
  }
}

// ===========================================================================
// Tensor-core flash attention, cp.async double-buffered, flat softmax,
// bitmask streamed through the pipeline.
// CHANGE vs R12: ONE __syncthreads per key-tile (was 2). The trailing stage
// guard is provably redundant: loads(it+1) overwrite stage (it+1)&1, last
// read in compute(it-1), which all warps completed before the top-of-it sync.
// ===========================================================================
namespace {
constexpr int AQ = 0;
constexpr int AK = 9216;
constexpr int AV = 18432;
constexpr int AM = 27648;
constexpr int ATTN_SMEM = 28160 * 4;   // 112640 B
constexpr float EXC = 0.125f * 1.4426950408889634f;  // (1/8)*log2(e)
}

__global__ __launch_bounds__(256, 2)
void attn_mma() {
  extern __shared__ uint32_t smem[];
  const uint32_t sb = smem_u32(smem);
  const int qt = blockIdx.x, h = blockIdx.y, b = blockIdx.z;
  const int tid = threadIdx.x;
  const int lane = tid & 31, w = tid >> 5;
  const int g = lane >> 2, t = lane & 3;
  const int bh = b * H_ + h;
  const uint32_t* const Qsh = g_Qph + ((size_t)bh * S_ + qt * 128) * 32;
  const uint32_t* const Qsl = g_Qpl + ((size_t)bh * S_ + qt * 128) * 32;
  const uint32_t* const Ksh = g_Kph + (size_t)bh * S_ * 32;
  const uint32_t* const Ksl = g_Kpl + (size_t)bh * S_ * 32;
  const uint32_t* const Vsh = g_Vph + (size_t)bh * (S_ / 2) * 64;
  const uint32_t* const Vsl = g_Vpl + (size_t)bh * (S_ / 2) * 64;
  const uint32_t* const Mb = g_mbits + (size_t)(b * S_ + qt * 128) * (S_ / 32);

  // ---- prologue: Q tile + key-tile 0 (K, V, mask) into stage 0 ----
#pragma unroll
  for (int l = 0; l < 4; l++) {
    int idx = tid + l * 256;        // 0..1023
    int r = idx >> 3, c = (idx & 7) * 4;
    cpasync16(sb + (AQ + r * R4 + c) * 4, Qsh + r * 32 + c);
    cpasync16(sb + (AQ + 4608 + r * R4 + c) * 4, Qsl + r * 32 + c);
  }
#pragma unroll
  for (int l = 0; l < 2; l++) {
    int idx = tid + l * 256;      // 0..511
    int r = idx >> 3, c = (idx & 7) * 4;
    uint32_t d = sb + (AK + r * R4 + c) * 4;
    cpasync16(d, Ksh + r * 32 + c);
    cpasync16(d + 2304 * 4, Ksl + r * 32 + c);
    int rv = idx >> 4, cv = (idx & 15) * 4;
    uint32_t dv = sb + (AV + rv * 72 + cv) * 4;
    cpasync16(dv, Vsh + rv * 64 + cv);
    cpasync16(dv + 2304 * 4, Vsl + rv * 64 + cv);
  }
  if (tid < 128)
    cpasync8(sb + (AM + tid * 2) * 4, Mb + (size_t)tid * (S_ / 32));
  CPA_COMMIT();

  float ls0 = 0.f, ls1 = 0.f;
  float oacc[8][4];
#pragma unroll
  for (int jd = 0; jd < 8; jd++)
#pragma unroll
    for (int c = 0; c < 4; c++) oacc[jd][c] = 0.f;

  const uint32_t* const Qbh = smem + AQ + (w * 16) * R4;
  const uint32_t* const Qbl = Qbh + 4608;

  for (int it = 0; it < S_ / 64; ++it) {
    CPA_WAIT(0);          // this tile's loads complete (per-thread)
    __syncthreads();      // visible to all; also gates stage reuse below

    if (it + 1 < S_ / 64) {
      const int kn = (it + 1) * 64;
      const int st = (it + 1) & 1;
#pragma unroll
      for (int l = 0; l < 2; l++) {
        int idx = tid + l * 256;
        int r = idx >> 3, c = (idx & 7) * 4;
        uint32_t d = sb + (AK + st * 4608 + r * R4 + c) * 4;
        cpasync16(d, Ksh + (size_t)(kn + r) * 32 + c);
        cpasync16(d + 2304 * 4, Ksl + (size_t)(kn + r) * 32 + c);
        int rv = idx >> 4, cv = (idx & 15) * 4;
        uint32_t dv = sb + (AV + st * 4608 + rv * 72 + cv) * 4;
        cpasync16(dv, Vsh + (size_t)(kn / 2 + rv) * 64 + cv);
        cpasync16(dv + 2304 * 4, Vsl + (size_t)(kn / 2 + rv) * 64 + cv);
      }
      if (tid < 128)
        cpasync8(sb + (AM + st * 256 + tid * 2) * 4,
                 Mb + (size_t)tid * (S_ / 32) + 2 * (it + 1));
      CPA_COMMIT();
    }

    const uint32_t* const Khi = smem + AK + (it & 1) * 4608;
    const uint32_t* const Klo = Khi + 2304;
    const uint32_t* const Vhp = smem + AV + (it & 1) * 4608;
    const uint32_t* const Vlp = Vhp + 2304;

    // mask bits for this tile (rows g and g+8)
    const uint32_t* const Mst = smem + AM + (it & 1) * 256;
    uint2 mg  = *(const uint2*)&Mst[(w * 16 + g) * 2];
    uint2 mg8 = *(const uint2*)&Mst[(w * 16 + g + 8) * 2];

    // ---- S = Q K^T (3-MMA split) ----
    float sf[8][4];
#pragma unroll
    for (int j = 0; j < 8; j++)
#pragma unroll
      for (int c = 0; c < 4; c++) sf[j][c] = 0.f;

#pragma unroll
    for (int ks = 0; ks < 4; ++ks) {
      const int kb = ks * 8;
      uint32_t ah[4], al[4];
      ah[0] = Qbh[g * R4 + kb + t];       ah[1] = Qbh[(g + 8) * R4 + kb + t];
      ah[2] = Qbh[g * R4 + kb + t + 4];   ah[3] = Qbh[(g + 8) * R4 + kb + t + 4];
      al[0] = Qbl[g * R4 + kb + t];       al[1] = Qbl[(g + 8) * R4 + kb + t];
      al[2] = Qbl[g * R4 + kb + t + 4];   al[3] = Qbl[(g + 8) * R4 + kb + t + 4];
#pragma unroll
      for (int j = 0; j < 8; j++) {
        int o = (j * 8 + g) * R4 + kb + t;
        uint32_t bh2[2] = {Khi[o], Khi[o + 4]};
        uint32_t bl2[2] = {Klo[o], Klo[o + 4]};
        mma16816(sf[j], ah, bh2);
        mma16816(sf[j], ah, bl2);
        mma16816(sf[j], al, bh2);
      }
    }

    // ---- mask bits -> p = exp2(score*EXC) or 0; accumulate row sums ----
#pragma unroll
    for (int j = 0; j < 8; j++) {
      const int pos = 8 * (j & 3) + 2 * t;
      const uint32_t wg  = (j < 4) ? mg.x : mg.y;
      const uint32_t wg8 = (j < 4) ? mg8.x : mg8.y;
      sf[j][0] = ((wg >> pos) & 1u)       ? exp2f(sf[j][0] * EXC) : 0.f;
      sf[j][1] = ((wg >> (pos + 1)) & 1u) ? exp2f(sf[j][1] * EXC) : 0.f;
      sf[j][2] = ((wg8 >> pos) & 1u)      ? exp2f(sf[j][2] * EXC) : 0.f;
      sf[j][3] = ((wg8 >> (pos + 1)) & 1u)? exp2f(sf[j][3] * EXC) : 0.f;
      ls0 += sf[j][0] + sf[j][1];
      ls1 += sf[j][2] + sf[j][3];
    }

    // ---- O += P V (3-MMA split; P from registers) ----
#pragma unroll
    for (int ks = 0; ks < 4; ++ks) {
      uint32_t ah[4], al[4];
      split2(sf[2 * ks][0], sf[2 * ks][1], ah[0], al[0]);
      split2(sf[2 * ks][2], sf[2 * ks][3], ah[1], al[1]);
      split2(sf[2 * ks + 1][0], sf[2 * ks + 1][1], ah[2], al[2]);
      split2(sf[2 * ks + 1][2], sf[2 * ks + 1][3], ah[3], al[3]);
#pragma unroll
      for (int jd = 0; jd < 8; jd++) {
        int o = (ks * 8 + t) * 72 + jd * 8 + g;
        uint32_t bh2[2] = {Vhp[o], Vhp[o + 4 * 72]};
        uint32_t bl2[2] = {Vlp[o], Vlp[o + 4 * 72]};
        mma16816(oacc[jd], ah, bh2);
        mma16816(oacc[jd], ah, bl2);
        mma16816(oacc[jd], al, bh2);
      }
    }
    // no trailing sync: next overwrite targets the *other* stage, and the
    // stage reused at it+2 is gated by the top-of-loop sync at it+1.
  }

  // ---- epilogue: reduce row sums across t-lanes, normalize, store ----
  ls0 += __shfl_xor_sync(0xffffffffu, ls0, 1);
  ls0 += __shfl_xor_sync(0xffffffffu, ls0, 2);
  ls1 += __shfl_xor_sync(0xffffffffu, ls1, 1);
  ls1 += __shfl_xor_sync(0xffffffffu, ls1, 2);
  float inv0 = 1.f / ls0, inv1 = 1.f / ls1;
  float* Op = g_Oh + ((size_t)bh * S_ + qt * 128 + w * 16) * DK_;
#pragma unroll
  for (int jd = 0; jd < 8; jd++) {
    *(float2*)(Op + (size_t)g * DK_ + jd * 8 + 2 * t) =
        make_float2(oacc[jd][0] * inv0, oacc[jd][1] * inv0);
    *(float2*)(Op + (size_t)(g + 8) * DK_ + jd * 8 + 2 * t) =
        make_float2(oacc[jd][2] * inv1, oacc[jd][3] * inv1);
  }
}

// ---------------------------------------------------------------------------
extern "C" void kernel_launch(void* const* d_in, const int* in_sizes, int n_in,
                              void* d_out, int out_size) {
  (void)in_sizes; (void)n_in; (void)out_size;
  const float* dec  = (const float*)d_in[0];
  const float* enc  = (const float*)d_in[1];
  const float* Wq   = (const float*)d_in[2];
  const float* Wkv  = (const float*)d_in[3];
  const float* Wo   = (const float*)d_in[4];
  const int*   mask = (const int*)d_in[5];
  float* out = (float*)d_out;

  float *Qp = nullptr, *KVp = nullptr, *attnp = nullptr;
  cudaGetSymbolAddress((void**)&Qp, g_Q);
  cudaGetSymbolAddress((void**)&KVp, g_KV);
  cudaGetSymbolAddress((void**)&attnp, g_attn);

  cudaFuncSetAttribute(gemm_tc, cudaFuncAttributeMaxDynamicSharedMemorySize, GEMM_SMEM);
  cudaFuncSetAttribute(attn_mma, cudaFuncAttributeMaxDynamicSharedMemorySize, ATTN_SMEM);

  const int M = B_ * S_;  // 4096
  // Launch order places the KV GEMM 4th: ncu captures the 4th launch.
  gemm_tc<<<dim3(DIM_ / 128, M / 128), 256, GEMM_SMEM>>>(dec, Wq, Qp, DIM_);
  mask_pack<<<B_ * S_ * (S_ / 32) / (32 * 8), 256>>>(mask);
  dummy_k<<<1, 32>>>();
  gemm_tc<<<dim3(2 * DIM_ / 128, M / 128), 256, GEMM_SMEM>>>(enc, Wkv, KVp, 2 * DIM_);
  repack_qkv<<<M / 2, 256>>>();
  attn_mma<<<dim3(S_ / 128, H_, B_), 256, ATTN_SMEM>>>();
  unpack_o<<<M, 256>>>();
  gemm_tc<<<dim3(DIM_ / 128, M / 128), 256, GEMM_SMEM>>>(attnp, Wo, out, DIM_);
}